// round 12
// baseline (speedup 1.0000x reference)
#include <cuda_runtime.h>
#include <cuda_bf16.h>
#include <math.h>
#include <cstdint>

typedef unsigned long long ull;

#define Bb 64
#define Tt 1024
#define Ii 256
#define Hh 512
#define Gg 2048

// ---- scratch (device globals) ----
__device__ float g_XP[(size_t)Tt * Gg * Bb];
__device__ float g_OUT0[(size_t)Tt * Hh * Bb];
__device__ float g_h[2][Hh * Bb];
__device__ unsigned g_ctr[512];
__device__ __nv_bfloat16 g_Whi[(size_t)Gg * Hh], g_Wlo[(size_t)Gg * Hh];
__device__ __nv_bfloat16 g_Xhi[(size_t)Tt * Bb * Hh], g_Xlo[(size_t)Tt * Bb * Hh];

__device__ __forceinline__ ull ffma2(ull a, ull b, ull c) {
    ull d;
    asm("fma.rn.f32x2 %0, %1, %2, %3;" : "=l"(d) : "l"(a), "l"(b), "l"(c));
    return d;
}
__device__ __forceinline__ ull splat2(float v) {
    ull d;
    asm("mov.b64 %0, {%1, %1};" : "=l"(d) : "f"(v));
    return d;
}
__device__ __forceinline__ float tanhapx(float x) {
    float y; asm("tanh.approx.f32 %0, %1;" : "=f"(y) : "f"(x)); return y;
}
__device__ __forceinline__ float sigapx(float x) { return 0.5f * tanhapx(0.5f * x) + 0.5f; }
__device__ __forceinline__ unsigned ldacq(const unsigned* p) {
    unsigned v; asm volatile("ld.global.acquire.gpu.b32 %0, [%1];" : "=r"(v) : "l"(p)); return v;
}
__device__ __forceinline__ void redrel(unsigned* p) {
    asm volatile("red.release.gpu.global.add.u32 [%0], 1;" :: "l"(p));
}
__device__ __forceinline__ void mma16816(float* d, const uint32_t* a, const uint32_t* b) {
    asm volatile(
        "mma.sync.aligned.m16n8k16.row.col.f32.bf16.bf16.f32 "
        "{%0,%1,%2,%3}, {%4,%5,%6,%7}, {%8,%9}, {%0,%1,%2,%3};"
        : "+f"(d[0]), "+f"(d[1]), "+f"(d[2]), "+f"(d[3])
        : "r"(a[0]), "r"(a[1]), "r"(a[2]), "r"(a[3]), "r"(b[0]), "r"(b[1]));
}

// ---- split W: fp32 [g][k] -> bf16 hi/lo ----
__global__ void k_splitW(const float* __restrict__ W, int n) {
    int i = blockIdx.x * 256 + threadIdx.x;
    if (i < n) {
        float v = W[i];
        __nv_bfloat16 h = __float2bfloat16(v);
        g_Whi[i] = h;
        g_Wlo[i] = __float2bfloat16(v - __bfloat162float(h));
    }
}

// ---- split+transpose x[b][k][t] -> Xhi/lo[t][b][k] (K=Ii) ----
__global__ void k_splitX0(const float* __restrict__ x) {
    __shared__ float tile[32][33];
    int t0 = blockIdx.x * 32, k0 = blockIdx.y * 32, b = blockIdx.z;
    int tx = threadIdx.x, ty = threadIdx.y;
    tile[ty][tx] = x[((size_t)b * Ii + k0 + ty) * Tt + t0 + tx];
    __syncthreads();
    float v = tile[tx][ty];
    size_t d = ((size_t)(t0 + ty) * Bb + b) * Ii + k0 + tx;
    __nv_bfloat16 h = __float2bfloat16(v);
    g_Xhi[d] = h;
    g_Xlo[d] = __float2bfloat16(v - __bfloat162float(h));
}

// ---- split+transpose OUT0[t][h][b] -> Xhi/lo[t][b][h] (K=Hh) ----
__global__ void k_splitH() {
    __shared__ float tile[32][33];
    int h0 = blockIdx.x * 32, b0 = blockIdx.y * 32, t = blockIdx.z;
    int tx = threadIdx.x, ty = threadIdx.y;
    tile[ty][tx] = g_OUT0[((size_t)t * Hh + h0 + ty) * Bb + b0 + tx];
    __syncthreads();
    float v = tile[tx][ty];
    size_t d = ((size_t)t * Bb + b0 + ty) * Hh + h0 + tx;
    __nv_bfloat16 h = __float2bfloat16(v);
    g_Xhi[d] = h;
    g_Xlo[d] = __float2bfloat16(v - __bfloat162float(h));
}

// ---- HMMA input GEMM: XP[t][g][b] = W·X + bias, bf16 hi/lo split ----
// block = (128 g-rows, 1 timestep), 8 warps x m16. n = batch 64 (8 n-tiles).
// Fragments loaded straight from global (layouts match mma maps); W L2-resident,
// B tile (128KB) L1-resident.
__global__ void __launch_bounds__(256) k_mma(const float* __restrict__ bih,
                                             const float* __restrict__ bhh, int KD) {
    const int tid = threadIdx.x, wid = tid >> 5, lane = tid & 31;
    const int g0 = blockIdx.x * 128, t = blockIdx.y;
    const int K2 = KD >> 1;               // u32 words per row
    const int r = lane >> 2, cw = lane & 3;
    const int gr = g0 + wid * 16 + r;

    const uint32_t* Ah = (const uint32_t*)g_Whi + (size_t)gr * K2 + cw;
    const uint32_t* Al = (const uint32_t*)g_Wlo + (size_t)gr * K2 + cw;
    const uint32_t* Bh = (const uint32_t*)g_Xhi + ((size_t)t * Bb + r) * K2 + cw;
    const uint32_t* Bl = (const uint32_t*)g_Xlo + ((size_t)t * Bb + r) * K2 + cw;
    const size_t row8 = (size_t)8 * K2;

    float acc[8][4];
#pragma unroll
    for (int nt = 0; nt < 8; nt++)
#pragma unroll
        for (int i = 0; i < 4; i++) acc[nt][i] = 0.0f;

    const int nks = KD >> 4;
    for (int ks = 0; ks < nks; ks++) {
        const int kw = ks * 8;
        uint32_t ah[4], al[4];
        ah[0] = Ah[kw];        ah[1] = Ah[row8 + kw];
        ah[2] = Ah[kw + 4];    ah[3] = Ah[row8 + kw + 4];
        al[0] = Al[kw];        al[1] = Al[row8 + kw];
        al[2] = Al[kw + 4];    al[3] = Al[row8 + kw + 4];
#pragma unroll
        for (int nt = 0; nt < 8; nt++) {
            const uint32_t* bp = Bh + (size_t)nt * row8;
            const uint32_t* bq = Bl + (size_t)nt * row8;
            uint32_t bh[2] = {bp[kw], bp[kw + 4]};
            uint32_t bl2[2] = {bq[kw], bq[kw + 4]};
            mma16816(acc[nt], ah, bh);
            mma16816(acc[nt], ah, bl2);
            mma16816(acc[nt], al, bh);
        }
    }

    const float bias0 = bih[gr] + bhh[gr];
    const float bias8 = bih[gr + 8] + bhh[gr + 8];
    float* dst0 = g_XP + ((size_t)t * Gg + gr) * Bb;
    float* dst8 = dst0 + (size_t)8 * Bb;
#pragma unroll
    for (int nt = 0; nt < 8; nt++) {
        const int b = nt * 8 + 2 * cw;
        *(float2*)(dst0 + b) = make_float2(acc[nt][0] + bias0, acc[nt][1] + bias0);
        *(float2*)(dst8 + b) = make_float2(acc[nt][2] + bias8, acc[nt][3] + bias8);
    }
}

// ---- out transpose: g_OUT0[t][h][b] -> out[b][t][h] ----
__global__ void k_tro(float* __restrict__ out) {
    __shared__ float tile[32][33];
    int h0 = blockIdx.x * 32, b0 = blockIdx.y * 32, t = blockIdx.z;
    int tx = threadIdx.x, ty = threadIdx.y;
    tile[ty][tx] = g_OUT0[((size_t)t * Hh + h0 + ty) * Bb + b0 + tx];
    __syncthreads();
    out[((size_t)(b0 + ty) * Tt + t) * Hh + h0 + tx] = tile[tx][ty];
}

// ---- reset: counters + h0 ----
__global__ void k_reset() {
    int tid = blockIdx.x * blockDim.x + threadIdx.x;
    if (tid < 512) g_ctr[tid] = 0u;
    if (tid < Hh * Bb) g_h[0][tid] = 0.0f;
}

// ---- persistent recurrence: 128 blocks x 512 thr (unchanged from R9) ----
__global__ void __launch_bounds__(512, 1) k_rec(const float* __restrict__ Whh,
                                                float* __restrict__ slab,
                                                float* __restrict__ dout, int layer) {
    extern __shared__ float sm[];
    float* Wt = sm;
    float* red = sm + 8192;
    const int tid = threadIdx.x;
    const int j = blockIdx.x;
    const int ko = tid >> 6, b = tid & 63;
    const int kb = ko * 64;
    const int hh = ko & 3;

    for (int idx = tid; idx < 8192; idx += 512) {
        int r = idx & 15, k = idx >> 4;
        Wt[idx] = Whh[(size_t)((r >> 2) * Hh + j * 4 + (r & 3)) * Hh + k];
    }
    __syncthreads();

    float c_reg = 0.0f;
    const int hi = j * 4 + hh;
    float* outHid = dout + (size_t)Bb * Tt * Hh + (size_t)layer * Bb * Hh;
    float* outCell = outHid + 2 * (size_t)Bb * Hh;
    unsigned* myctr = &g_ctr[(j >> 4) * 64];
    const unsigned* pollctr = &g_ctr[ko * 64];

    for (int t = 0; t < Tt; t++) {
        const float* hR = g_h[t & 1];
        const float* xpt = g_XP + (size_t)t * Gg * Bb;

        float xv[4];
        if (tid < 256) {
#pragma unroll
            for (int q = 0; q < 4; q++)
                xv[q] = __ldcg(&xpt[(size_t)(q * Hh + hi) * Bb + b]);
        }
        {
            const unsigned tgt = 16u * (unsigned)t;
            if ((tid & 31) == 0) {
                while (ldacq(pollctr) < tgt) { }
            }
            __syncwarp();
        }

        ull acc[8];
#pragma unroll
        for (int i = 0; i < 8; i++) acc[i] = 0ull;

        float hv[2][8];
#pragma unroll
        for (int u = 0; u < 8; u++)
            hv[0][u] = __ldcg(&hR[(kb + u) * Bb + b]);

#pragma unroll
        for (int kc = 0; kc < 8; kc++) {
            const int cur = kc & 1;
            if (kc < 7) {
#pragma unroll
                for (int u = 0; u < 8; u++)
                    hv[cur ^ 1][u] = __ldcg(&hR[(kb + (kc + 1) * 8 + u) * Bb + b]);
            }
#pragma unroll
            for (int u = 0; u < 8; u++) {
                ull hp = splat2(hv[cur][u]);
                const float* wk = Wt + (kb + kc * 8 + u) * 16;
#pragma unroll
                for (int i = 0; i < 4; i++) {
                    ulonglong2 w2 = *(const ulonglong2*)(wk + 4 * i);
                    acc[2 * i] = ffma2(w2.x, hp, acc[2 * i]);
                    acc[2 * i + 1] = ffma2(w2.y, hp, acc[2 * i + 1]);
                }
            }
        }
        {
            float* rp = red + (ko * 64 + b) * 17;
            const float* af = (const float*)acc;
#pragma unroll
            for (int r = 0; r < 16; r++) rp[r] = af[r];
        }
        __syncthreads();

        if (tid < 256) {
            float gv[4];
#pragma unroll
            for (int q = 0; q < 4; q++) {
                float s = xv[q];
#pragma unroll
                for (int k2 = 0; k2 < 8; k2++) s += red[(k2 * 64 + b) * 17 + q * 4 + hh];
                gv[q] = s;
            }
            float ig = sigapx(gv[0]), fg = sigapx(gv[1]);
            float gg = tanhapx(gv[2]), og = sigapx(gv[3]);
            c_reg = fg * c_reg + ig * gg;
            float hval = og * tanhapx(c_reg);
            __stcg(&g_h[(t + 1) & 1][hi * Bb + b], hval);
            __stcg(&slab[((size_t)t * Hh + hi) * Bb + b], hval);
            if (t == Tt - 1) {
                outHid[(size_t)b * Hh + hi] = hval;
                outCell[(size_t)b * Hh + hi] = c_reg;
            }
        }
        __syncthreads();
        if (tid == 0) redrel(myctr);
    }
}

extern "C" void kernel_launch(void* const* d_in, const int* in_sizes, int n_in,
                              void* d_out, int out_size) {
    const float* x = (const float*)d_in[0];
    const float* Wih0 = (const float*)d_in[1];
    const float* Whh0 = (const float*)d_in[2];
    const float* bih0 = (const float*)d_in[3];
    const float* bhh0 = (const float*)d_in[4];
    const float* Wih1 = (const float*)d_in[5];
    const float* Whh1 = (const float*)d_in[6];
    const float* bih1 = (const float*)d_in[7];
    const float* bhh1 = (const float*)d_in[8];
    float* out = (float*)d_out;

    float* out0;
    cudaGetSymbolAddress((void**)&out0, g_OUT0);

    const int recSmem = (8192 + 8 * 64 * 17) * 4;
    cudaFuncSetAttribute(k_rec, cudaFuncAttributeMaxDynamicSharedMemorySize, recSmem);

    dim3 thr32(32, 32);

    // layer 0
    k_splitW<<<(Gg * Ii + 255) / 256, 256>>>(Wih0, Gg * Ii);
    k_splitX0<<<dim3(Tt / 32, Ii / 32, Bb), thr32>>>(x);
    k_mma<<<dim3(Gg / 128, Tt), 256>>>(bih0, bhh0, Ii);
    k_reset<<<128, 256>>>();
    k_rec<<<128, 512, recSmem>>>(Whh0, out0, out, 0);

    // layer 1
    k_splitW<<<(Gg * Hh + 255) / 256, 256>>>(Wih1, Gg * Hh);
    k_splitH<<<dim3(Hh / 32, Bb / 32, Tt), thr32>>>();
    k_mma<<<dim3(Gg / 128, Tt), 256>>>(bih1, bhh1, Hh);
    k_reset<<<128, 256>>>();
    k_rec<<<128, 512, recSmem>>>(Whh1, out0, out, 1);

    // final transpose to out[b][t][h]
    k_tro<<<dim3(Hh / 32, Bb / 32, Tt), thr32>>>(out);
}

// round 13
// speedup vs baseline: 1.3495x; 1.3495x over previous
#include <cuda_runtime.h>
#include <cuda_bf16.h>
#include <math.h>
#include <cstdint>

typedef unsigned long long ull;

#define Bb 64
#define Tt 1024
#define Ii 256
#define Hh 512
#define Gg 2048

// ---- scratch (device globals) ----
__device__ float g_XP[(size_t)Tt * Gg * Bb];
__device__ float g_OUT0[(size_t)Tt * Hh * Bb];
__device__ float g_h[2][Hh * Bb];
__device__ unsigned g_ctr[512];
__device__ __nv_bfloat16 g_Whi[(size_t)Gg * Hh], g_Wlo[(size_t)Gg * Hh];
__device__ __nv_bfloat16 g_Xhi[(size_t)Tt * Bb * Hh], g_Xlo[(size_t)Tt * Bb * Hh];

__device__ __forceinline__ ull ffma2(ull a, ull b, ull c) {
    ull d;
    asm("fma.rn.f32x2 %0, %1, %2, %3;" : "=l"(d) : "l"(a), "l"(b), "l"(c));
    return d;
}
__device__ __forceinline__ ull splat2(float v) {
    ull d;
    asm("mov.b64 %0, {%1, %1};" : "=l"(d) : "f"(v));
    return d;
}
__device__ __forceinline__ float tanhapx(float x) {
    float y; asm("tanh.approx.f32 %0, %1;" : "=f"(y) : "f"(x)); return y;
}
__device__ __forceinline__ float sigapx(float x) { return 0.5f * tanhapx(0.5f * x) + 0.5f; }
__device__ __forceinline__ unsigned ldacq(const unsigned* p) {
    unsigned v; asm volatile("ld.global.acquire.gpu.b32 %0, [%1];" : "=r"(v) : "l"(p)); return v;
}
__device__ __forceinline__ void redrel(unsigned* p) {
    asm volatile("red.release.gpu.global.add.u32 [%0], 1;" :: "l"(p));
}
__device__ __forceinline__ uint32_t s2u(const void* p) {
    uint32_t a;
    asm("{ .reg .u64 t; cvta.to.shared.u64 t, %1; cvt.u32.u64 %0, t; }" : "=r"(a) : "l"(p));
    return a;
}
__device__ __forceinline__ void mma16816(float* d, const uint32_t* a, const uint32_t* b) {
    asm volatile(
        "mma.sync.aligned.m16n8k16.row.col.f32.bf16.bf16.f32 "
        "{%0,%1,%2,%3}, {%4,%5,%6,%7}, {%8,%9}, {%0,%1,%2,%3};"
        : "+f"(d[0]), "+f"(d[1]), "+f"(d[2]), "+f"(d[3])
        : "r"(a[0]), "r"(a[1]), "r"(a[2]), "r"(a[3]), "r"(b[0]), "r"(b[1]));
}
__device__ __forceinline__ void ldmx4(uint32_t* r, uint32_t addr) {
    asm volatile("ldmatrix.sync.aligned.m8n8.x4.shared.b16 {%0,%1,%2,%3}, [%4];"
                 : "=r"(r[0]), "=r"(r[1]), "=r"(r[2]), "=r"(r[3]) : "r"(addr));
}
// smem tile: 128 rows x 64B (32 bf16). seg s (16B) swizzled by row for
// conflict-free ldmatrix (rows 0..7 hit 8 distinct bank groups).
__device__ __forceinline__ uint32_t swoff(int r, int s) {
    return (uint32_t)(r * 64 + (((s ^ ((r >> 1) & 3)) & 3) << 4));
}

// ---- split W: fp32 [g][k] -> bf16 hi/lo ----
__global__ void k_splitW(const float* __restrict__ W, int n) {
    int i = blockIdx.x * 256 + threadIdx.x;
    if (i < n) {
        float v = W[i];
        __nv_bfloat16 h = __float2bfloat16(v);
        g_Whi[i] = h;
        g_Wlo[i] = __float2bfloat16(v - __bfloat162float(h));
    }
}

// ---- split+transpose x[b][k][t] -> Xhi/lo[t][b][k] (K=Ii) ----
__global__ void k_splitX0(const float* __restrict__ x) {
    __shared__ float tile[32][33];
    int t0 = blockIdx.x * 32, k0 = blockIdx.y * 32, b = blockIdx.z;
    int tx = threadIdx.x, ty = threadIdx.y;
    tile[ty][tx] = x[((size_t)b * Ii + k0 + ty) * Tt + t0 + tx];
    __syncthreads();
    float v = tile[tx][ty];
    size_t d = ((size_t)(t0 + ty) * Bb + b) * Ii + k0 + tx;
    __nv_bfloat16 h = __float2bfloat16(v);
    g_Xhi[d] = h;
    g_Xlo[d] = __float2bfloat16(v - __bfloat162float(h));
}

// ---- split+transpose OUT0[t][h][b] -> Xhi/lo[t][b][h] (K=Hh) ----
__global__ void k_splitH() {
    __shared__ float tile[32][33];
    int h0 = blockIdx.x * 32, b0 = blockIdx.y * 32, t = blockIdx.z;
    int tx = threadIdx.x, ty = threadIdx.y;
    tile[ty][tx] = g_OUT0[((size_t)t * Hh + h0 + ty) * Bb + b0 + tx];
    __syncthreads();
    float v = tile[tx][ty];
    size_t d = ((size_t)t * Bb + b0 + ty) * Hh + h0 + tx;
    __nv_bfloat16 h = __float2bfloat16(v);
    g_Xhi[d] = h;
    g_Xlo[d] = __float2bfloat16(v - __bfloat162float(h));
}

// ---- HMMA input GEMM: XP[t][g][b] = W·X + bias, bf16 hi/lo split ----
// block = 128 g-rows x 2 timesteps (N=128). smem-staged k-chunks of 32,
// fragments via ldmatrix. 8 warps x m16; 16 n-tiles each.
__global__ void __launch_bounds__(256) k_mma(const float* __restrict__ bih,
                                             const float* __restrict__ bhh, int KD) {
    __shared__ uint8_t smb[32768];   // Ahi 8K | Alo 8K | Bhi 8K | Blo 8K
    const uint32_t sb = s2u(smb);
    const int tid = threadIdx.x, wid = tid >> 5, lane = tid & 31;
    const int g0 = blockIdx.x * 128, t0 = blockIdx.y * 2;
    const int K2 = KD >> 1;          // u32 words per row
    const int nc = KD >> 5;          // k-chunks of 32

    const uint32_t* Whi = (const uint32_t*)g_Whi;
    const uint32_t* Wlo = (const uint32_t*)g_Wlo;
    const uint32_t* Xhi = (const uint32_t*)g_Xhi;
    const uint32_t* Xlo = (const uint32_t*)g_Xlo;

    float acc[16][4];
#pragma unroll
    for (int q = 0; q < 16; q++)
#pragma unroll
        for (int i = 0; i < 4; i++) acc[q][i] = 0.0f;

    // ldmatrix lane address components (constant over chunks)
    const int arow = wid * 16 + (lane & 15);
    const int aseg = lane >> 4;                       // + 2*ks2
    const int bsub = ((lane >> 4) << 3) + (lane & 7); // row within 16-row pair
    const int bseg = (lane >> 3) & 1;                 // + 2*ks2

    for (int c = 0; c < nc; c++) {
        __syncthreads();
        // stage A (128 r x 4 seg per split): 2 float4 per thread per split
#pragma unroll
        for (int i = 0; i < 2; i++) {
            int idx = i * 256 + tid, r = idx >> 2, s = idx & 3;
            size_t gw = (size_t)(g0 + r) * K2 + c * 16 + s * 4;
            uint32_t so = swoff(r, s);
            *(float4*)(smb + so) = *(const float4*)(Whi + gw);
            *(float4*)(smb + 8192 + so) = *(const float4*)(Wlo + gw);
        }
        // stage B (128 rows = 2t x 64b)
#pragma unroll
        for (int i = 0; i < 2; i++) {
            int idx = i * 256 + tid, r = idx >> 2, s = idx & 3;
            int t = t0 + (r >> 6), b = r & 63;
            size_t gw = ((size_t)t * Bb + b) * K2 + c * 16 + s * 4;
            uint32_t so = swoff(r, s);
            *(float4*)(smb + 16384 + so) = *(const float4*)(Xhi + gw);
            *(float4*)(smb + 24576 + so) = *(const float4*)(Xlo + gw);
        }
        __syncthreads();

#pragma unroll
        for (int ks2 = 0; ks2 < 2; ks2++) {
            uint32_t ah[4], al[4];
            {
                uint32_t ao = swoff(arow, 2 * ks2 + aseg);
                ldmx4(ah, sb + ao);
                ldmx4(al, sb + 8192 + ao);
            }
#pragma unroll
            for (int p = 0; p < 8; p++) {
                uint32_t bh[4], bl[4];
                uint32_t bo = swoff(p * 16 + bsub, 2 * ks2 + bseg);
                ldmx4(bh, sb + 16384 + bo);
                ldmx4(bl, sb + 24576 + bo);
                mma16816(acc[2 * p], ah, bh);
                mma16816(acc[2 * p], ah, bl);
                mma16816(acc[2 * p], al, bh);
                mma16816(acc[2 * p + 1], ah, bh + 2);
                mma16816(acc[2 * p + 1], ah, bl + 2);
                mma16816(acc[2 * p + 1], al, bh + 2);
            }
        }
    }

    // epilogue
    const int gr = g0 + wid * 16 + (lane >> 2);
    const float bias0 = bih[gr] + bhh[gr];
    const float bias8 = bih[gr + 8] + bhh[gr + 8];
    const int cw = lane & 3;
#pragma unroll
    for (int q = 0; q < 16; q++) {
        const int nb = q * 8;                 // row base in B tile (0..120)
        const int t = t0 + (nb >> 6);
        const int b0 = (nb & 63) + 2 * cw;
        float* dst = g_XP + ((size_t)t * Gg + gr) * Bb + b0;
        *(float2*)dst = make_float2(acc[q][0] + bias0, acc[q][1] + bias0);
        *(float2*)(dst + (size_t)8 * Bb) = make_float2(acc[q][2] + bias8, acc[q][3] + bias8);
    }
}

// ---- out transpose: g_OUT0[t][h][b] -> out[b][t][h] ----
__global__ void k_tro(float* __restrict__ out) {
    __shared__ float tile[32][33];
    int h0 = blockIdx.x * 32, b0 = blockIdx.y * 32, t = blockIdx.z;
    int tx = threadIdx.x, ty = threadIdx.y;
    tile[ty][tx] = g_OUT0[((size_t)t * Hh + h0 + ty) * Bb + b0 + tx];
    __syncthreads();
    out[((size_t)(b0 + ty) * Tt + t) * Hh + h0 + tx] = tile[tx][ty];
}

// ---- reset: counters + h0 ----
__global__ void k_reset() {
    int tid = blockIdx.x * blockDim.x + threadIdx.x;
    if (tid < 512) g_ctr[tid] = 0u;
    if (tid < Hh * Bb) g_h[0][tid] = 0.0f;
}

// ---- persistent recurrence: 128 blocks x 512 thr (unchanged from R9) ----
__global__ void __launch_bounds__(512, 1) k_rec(const float* __restrict__ Whh,
                                                float* __restrict__ slab,
                                                float* __restrict__ dout, int layer) {
    extern __shared__ float sm[];
    float* Wt = sm;
    float* red = sm + 8192;
    const int tid = threadIdx.x;
    const int j = blockIdx.x;
    const int ko = tid >> 6, b = tid & 63;
    const int kb = ko * 64;
    const int hh = ko & 3;

    for (int idx = tid; idx < 8192; idx += 512) {
        int r = idx & 15, k = idx >> 4;
        Wt[idx] = Whh[(size_t)((r >> 2) * Hh + j * 4 + (r & 3)) * Hh + k];
    }
    __syncthreads();

    float c_reg = 0.0f;
    const int hi = j * 4 + hh;
    float* outHid = dout + (size_t)Bb * Tt * Hh + (size_t)layer * Bb * Hh;
    float* outCell = outHid + 2 * (size_t)Bb * Hh;
    unsigned* myctr = &g_ctr[(j >> 4) * 64];
    const unsigned* pollctr = &g_ctr[ko * 64];

    for (int t = 0; t < Tt; t++) {
        const float* hR = g_h[t & 1];
        const float* xpt = g_XP + (size_t)t * Gg * Bb;

        float xv[4];
        if (tid < 256) {
#pragma unroll
            for (int q = 0; q < 4; q++)
                xv[q] = __ldcg(&xpt[(size_t)(q * Hh + hi) * Bb + b]);
        }
        {
            const unsigned tgt = 16u * (unsigned)t;
            if ((tid & 31) == 0) {
                while (ldacq(pollctr) < tgt) { }
            }
            __syncwarp();
        }

        ull acc[8];
#pragma unroll
        for (int i = 0; i < 8; i++) acc[i] = 0ull;

        float hv[2][8];
#pragma unroll
        for (int u = 0; u < 8; u++)
            hv[0][u] = __ldcg(&hR[(kb + u) * Bb + b]);

#pragma unroll
        for (int kc = 0; kc < 8; kc++) {
            const int cur = kc & 1;
            if (kc < 7) {
#pragma unroll
                for (int u = 0; u < 8; u++)
                    hv[cur ^ 1][u] = __ldcg(&hR[(kb + (kc + 1) * 8 + u) * Bb + b]);
            }
#pragma unroll
            for (int u = 0; u < 8; u++) {
                ull hp = splat2(hv[cur][u]);
                const float* wk = Wt + (kb + kc * 8 + u) * 16;
#pragma unroll
                for (int i = 0; i < 4; i++) {
                    ulonglong2 w2 = *(const ulonglong2*)(wk + 4 * i);
                    acc[2 * i] = ffma2(w2.x, hp, acc[2 * i]);
                    acc[2 * i + 1] = ffma2(w2.y, hp, acc[2 * i + 1]);
                }
            }
        }
        {
            float* rp = red + (ko * 64 + b) * 17;
            const float* af = (const float*)acc;
#pragma unroll
            for (int r = 0; r < 16; r++) rp[r] = af[r];
        }
        __syncthreads();

        if (tid < 256) {
            float gv[4];
#pragma unroll
            for (int q = 0; q < 4; q++) {
                float s = xv[q];
#pragma unroll
                for (int k2 = 0; k2 < 8; k2++) s += red[(k2 * 64 + b) * 17 + q * 4 + hh];
                gv[q] = s;
            }
            float ig = sigapx(gv[0]), fg = sigapx(gv[1]);
            float gg = tanhapx(gv[2]), og = sigapx(gv[3]);
            c_reg = fg * c_reg + ig * gg;
            float hval = og * tanhapx(c_reg);
            __stcg(&g_h[(t + 1) & 1][hi * Bb + b], hval);
            __stcg(&slab[((size_t)t * Hh + hi) * Bb + b], hval);
            if (t == Tt - 1) {
                outHid[(size_t)b * Hh + hi] = hval;
                outCell[(size_t)b * Hh + hi] = c_reg;
            }
        }
        __syncthreads();
        if (tid == 0) redrel(myctr);
    }
}

extern "C" void kernel_launch(void* const* d_in, const int* in_sizes, int n_in,
                              void* d_out, int out_size) {
    const float* x = (const float*)d_in[0];
    const float* Wih0 = (const float*)d_in[1];
    const float* Whh0 = (const float*)d_in[2];
    const float* bih0 = (const float*)d_in[3];
    const float* bhh0 = (const float*)d_in[4];
    const float* Wih1 = (const float*)d_in[5];
    const float* Whh1 = (const float*)d_in[6];
    const float* bih1 = (const float*)d_in[7];
    const float* bhh1 = (const float*)d_in[8];
    float* out = (float*)d_out;

    float* out0;
    cudaGetSymbolAddress((void**)&out0, g_OUT0);

    const int recSmem = (8192 + 8 * 64 * 17) * 4;
    cudaFuncSetAttribute(k_rec, cudaFuncAttributeMaxDynamicSharedMemorySize, recSmem);

    dim3 thr32(32, 32);

    // layer 0
    k_splitW<<<(Gg * Ii + 255) / 256, 256>>>(Wih0, Gg * Ii);
    k_splitX0<<<dim3(Tt / 32, Ii / 32, Bb), thr32>>>(x);
    k_mma<<<dim3(Gg / 128, Tt / 2), 256>>>(bih0, bhh0, Ii);
    k_reset<<<128, 256>>>();
    k_rec<<<128, 512, recSmem>>>(Whh0, out0, out, 0);

    // layer 1
    k_splitW<<<(Gg * Hh + 255) / 256, 256>>>(Wih1, Gg * Hh);
    k_splitH<<<dim3(Hh / 32, Bb / 32, Tt), thr32>>>();
    k_mma<<<dim3(Gg / 128, Tt / 2), 256>>>(bih1, bhh1, Hh);
    k_reset<<<128, 256>>>();
    k_rec<<<128, 512, recSmem>>>(Whh1, out0, out, 1);

    // final transpose to out[b][t][h]
    k_tro<<<dim3(Hh / 32, Bb / 32, Tt), thr32>>>(out);
}

// round 15
// speedup vs baseline: 1.4503x; 1.0747x over previous
#include <cuda_runtime.h>
#include <cuda_bf16.h>
#include <math.h>
#include <cstdint>

typedef unsigned long long ull;

#define Bb 64
#define Tt 1024
#define Ii 256
#define Hh 512
#define Gg 2048

// ---- scratch (device globals) ----
__device__ float g_XP[(size_t)Tt * Gg * Bb];
__device__ float g_OUT0[(size_t)Tt * Hh * Bb];
__device__ unsigned g_ctr[512];
__device__ __nv_bfloat16 g_Whi[(size_t)Gg * Hh], g_Wlo[(size_t)Gg * Hh];
__device__ __nv_bfloat16 g_Xhi[(size_t)Tt * Bb * Hh], g_Xlo[(size_t)Tt * Bb * Hh];
__device__ __nv_bfloat16 g_hbh[2][Bb * Hh], g_hbl[2][Bb * Hh];

__device__ __forceinline__ float tanhapx(float x) {
    float y; asm("tanh.approx.f32 %0, %1;" : "=f"(y) : "f"(x)); return y;
}
__device__ __forceinline__ float sigapx(float x) { return 0.5f * tanhapx(0.5f * x) + 0.5f; }
__device__ __forceinline__ unsigned ldacq(const unsigned* p) {
    unsigned v; asm volatile("ld.global.acquire.gpu.b32 %0, [%1];" : "=r"(v) : "l"(p)); return v;
}
__device__ __forceinline__ void redrel(unsigned* p) {
    asm volatile("red.release.gpu.global.add.u32 [%0], 1;" :: "l"(p));
}
__device__ __forceinline__ uint32_t s2u(const void* p) {
    uint32_t a;
    asm("{ .reg .u64 t; cvta.to.shared.u64 t, %1; cvt.u32.u64 %0, t; }" : "=r"(a) : "l"(p));
    return a;
}
__device__ __forceinline__ void mma16816(float* d, const uint32_t* a, const uint32_t* b) {
    asm volatile(
        "mma.sync.aligned.m16n8k16.row.col.f32.bf16.bf16.f32 "
        "{%0,%1,%2,%3}, {%4,%5,%6,%7}, {%8,%9}, {%0,%1,%2,%3};"
        : "+f"(d[0]), "+f"(d[1]), "+f"(d[2]), "+f"(d[3])
        : "r"(a[0]), "r"(a[1]), "r"(a[2]), "r"(a[3]), "r"(b[0]), "r"(b[1]));
}
__device__ __forceinline__ void ldmx4(uint32_t* r, uint32_t addr) {
    asm volatile("ldmatrix.sync.aligned.m8n8.x4.shared.b16 {%0,%1,%2,%3}, [%4];"
                 : "=r"(r[0]), "=r"(r[1]), "=r"(r[2]), "=r"(r[3]) : "r"(addr));
}
// row-tile of 64B rows; 16B seg swizzled by row (validated in R12 k_mma)
__device__ __forceinline__ uint32_t swoff(int r, int s) {
    return (uint32_t)(r * 64 + (((s ^ ((r >> 1) & 3)) & 3) << 4));
}

// ---- split W: fp32 [g][k] -> bf16 hi/lo ----
__global__ void k_splitW(const float* __restrict__ W, int n) {
    int i = blockIdx.x * 256 + threadIdx.x;
    if (i < n) {
        float v = W[i];
        __nv_bfloat16 h = __float2bfloat16(v);
        g_Whi[i] = h;
        g_Wlo[i] = __float2bfloat16(v - __bfloat162float(h));
    }
}

// ---- split+transpose x[b][k][t] -> Xhi/lo[t][b][k] (K=Ii) ----
__global__ void k_splitX0(const float* __restrict__ x) {
    __shared__ float tile[32][33];
    int t0 = blockIdx.x * 32, k0 = blockIdx.y * 32, b = blockIdx.z;
    int tx = threadIdx.x, ty = threadIdx.y;
    tile[ty][tx] = x[((size_t)b * Ii + k0 + ty) * Tt + t0 + tx];
    __syncthreads();
    float v = tile[tx][ty];
    size_t d = ((size_t)(t0 + ty) * Bb + b) * Ii + k0 + tx;
    __nv_bfloat16 h = __float2bfloat16(v);
    g_Xhi[d] = h;
    g_Xlo[d] = __float2bfloat16(v - __bfloat162float(h));
}

// ---- HMMA input GEMM (unchanged from R12) ----
__global__ void __launch_bounds__(256) k_mma(const float* __restrict__ bih,
                                             const float* __restrict__ bhh, int KD) {
    __shared__ uint8_t smb[32768];
    const uint32_t sb = s2u(smb);
    const int tid = threadIdx.x, wid = tid >> 5, lane = tid & 31;
    const int g0 = blockIdx.x * 128, t0 = blockIdx.y * 2;
    const int K2 = KD >> 1;
    const int nc = KD >> 5;

    const uint32_t* Whi = (const uint32_t*)g_Whi;
    const uint32_t* Wlo = (const uint32_t*)g_Wlo;
    const uint32_t* Xhi = (const uint32_t*)g_Xhi;
    const uint32_t* Xlo = (const uint32_t*)g_Xlo;

    float acc[16][4];
#pragma unroll
    for (int q = 0; q < 16; q++)
#pragma unroll
        for (int i = 0; i < 4; i++) acc[q][i] = 0.0f;

    const int arow = wid * 16 + (lane & 15);
    const int aseg = lane >> 4;
    const int bsub = ((lane >> 4) << 3) + (lane & 7);
    const int bseg = (lane >> 3) & 1;

    for (int c = 0; c < nc; c++) {
        __syncthreads();
#pragma unroll
        for (int i = 0; i < 2; i++) {
            int idx = i * 256 + tid, r = idx >> 2, s = idx & 3;
            size_t gw = (size_t)(g0 + r) * K2 + c * 16 + s * 4;
            uint32_t so = swoff(r, s);
            *(float4*)(smb + so) = *(const float4*)(Whi + gw);
            *(float4*)(smb + 8192 + so) = *(const float4*)(Wlo + gw);
        }
#pragma unroll
        for (int i = 0; i < 2; i++) {
            int idx = i * 256 + tid, r = idx >> 2, s = idx & 3;
            int t = t0 + (r >> 6), b = r & 63;
            size_t gw = ((size_t)t * Bb + b) * K2 + c * 16 + s * 4;
            uint32_t so = swoff(r, s);
            *(float4*)(smb + 16384 + so) = *(const float4*)(Xhi + gw);
            *(float4*)(smb + 24576 + so) = *(const float4*)(Xlo + gw);
        }
        __syncthreads();

#pragma unroll
        for (int ks2 = 0; ks2 < 2; ks2++) {
            uint32_t ah[4], al[4];
            {
                uint32_t ao = swoff(arow, 2 * ks2 + aseg);
                ldmx4(ah, sb + ao);
                ldmx4(al, sb + 8192 + ao);
            }
#pragma unroll
            for (int p = 0; p < 8; p++) {
                uint32_t bh[4], bl[4];
                uint32_t bo = swoff(p * 16 + bsub, 2 * ks2 + bseg);
                ldmx4(bh, sb + 16384 + bo);
                ldmx4(bl, sb + 24576 + bo);
                mma16816(acc[2 * p], ah, bh);
                mma16816(acc[2 * p], ah, bl);
                mma16816(acc[2 * p], al, bh);
                mma16816(acc[2 * p + 1], ah, bh + 2);
                mma16816(acc[2 * p + 1], ah, bl + 2);
                mma16816(acc[2 * p + 1], al, bh + 2);
            }
        }
    }

    const int gr = g0 + wid * 16 + (lane >> 2);
    const float bias0 = bih[gr] + bhh[gr];
    const float bias8 = bih[gr + 8] + bhh[gr + 8];
    const int cw = lane & 3;
#pragma unroll
    for (int q = 0; q < 16; q++) {
        const int nb = q * 8;
        const int t = t0 + (nb >> 6);
        const int b0 = (nb & 63) + 2 * cw;
        float* dst = g_XP + ((size_t)t * Gg + gr) * Bb + b0;
        *(float2*)dst = make_float2(acc[q][0] + bias0, acc[q][1] + bias0);
        *(float2*)(dst + (size_t)8 * Bb) = make_float2(acc[q][2] + bias8, acc[q][3] + bias8);
    }
}

// ---- out transpose ----
__global__ void k_tro(float* __restrict__ out) {
    __shared__ float tile[32][33];
    int h0 = blockIdx.x * 32, b0 = blockIdx.y * 32, t = blockIdx.z;
    int tx = threadIdx.x, ty = threadIdx.y;
    tile[ty][tx] = g_OUT0[((size_t)t * Hh + h0 + ty) * Bb + b0 + tx];
    __syncthreads();
    out[((size_t)(b0 + ty) * Tt + t) * Hh + h0 + tx] = tile[tx][ty];
}

// ---- reset counters ----
__global__ void k_reset() {
    int tid = blockIdx.x * blockDim.x + threadIdx.x;
    if (tid < 512) g_ctr[tid] = 0u;
}

// ---- HMMA persistent recurrence: 128 blocks x 256 thr ----
// block j owns h 4j..4j+3 -> 16 gate rows (local r = q*4+hh). A = W_hh slice in
// smem bf16 hi/lo (static). B = h[t-1] staged per step (bf16 hi/lo, [b][k]).
// warp w: n-pair ntp=w&3 (16 b), k-quarters kq=(w>>2)*2+{0,1}. red over 4 kq.
__global__ void __launch_bounds__(256, 1) k_rec(const float* __restrict__ Whh,
                                                float* __restrict__ dout, int layer) {
    extern __shared__ uint8_t smx[];
    uint8_t* smA = smx;                  // Ahi 16K | Alo 16K
    uint8_t* smB = smx + 32768;          // Bhi 64K | Blo 64K
    float* red = (float*)(smx + 163840); // [4 kq][16 r][72]
    const uint32_t sbA = s2u(smA), sbB = s2u(smB);
    const int tid = threadIdx.x, w = tid >> 5, lane = tid & 31;
    const int j = blockIdx.x;
    const int hh = tid >> 6, b = tid & 63;   // activation role
    const int hi = j * 4 + hh;

    // stage A once: 16 rows x 512 k, bf16 hi/lo, chunked swizzle
    for (int idx = tid; idx < 8192; idx += 256) {
        int r = idx & 15, k = idx >> 4;
        float v = Whh[(size_t)((r >> 2) * Hh + j * 4 + (r & 3)) * Hh + k];
        __nv_bfloat16 hb = __float2bfloat16(v);
        __nv_bfloat16 lb = __float2bfloat16(v - __bfloat162float(hb));
        uint32_t off = (k >> 5) * 1024 + swoff(r, (k >> 3) & 3) + (k & 7) * 2;
        *(__nv_bfloat16*)(smA + off) = hb;
        *(__nv_bfloat16*)(smA + 16384 + off) = lb;
    }
    __syncthreads();

    const int ntp = w & 3;
    const int arow = lane & 15, aseg = lane >> 4;
    const int bsub = ((lane >> 4) << 3) + (lane & 7);
    const int bsegb = (lane >> 3) & 1;
    const int brow = ntp * 16 + bsub;
    const int bst = tid >> 2, bss = tid & 3;   // staging role

    float c_reg = 0.0f;
    float* outHid = dout + (size_t)Bb * Tt * Hh + (size_t)layer * Bb * Hh;
    float* outCell = outHid + 2 * (size_t)Bb * Hh;
    unsigned* myctr = &g_ctr[(j & 3) * 64];

    for (int t = 0; t < Tt; t++) {
        const float* xpt = g_XP + (size_t)t * Gg * Bb;
        float xv[4];
#pragma unroll
        for (int q = 0; q < 4; q++)
            xv[q] = __ldcg(&xpt[(size_t)(q * Hh + hi) * Bb + b]);

        if (t > 0) {
            // rendezvous: all 128 blocks published step t-1
            if (tid < 4) {
                const unsigned tgt = 32u * (unsigned)t;
                const unsigned* cp = &g_ctr[tid * 64];
                while (ldacq(cp) < tgt) { }
            }
            __syncthreads();
            // stage B: h[t-1] hi/lo, 64 rows x 512 k
            const uint32_t* srcH;
            const uint32_t* srcL;
            if (layer == 0) {
                srcH = (const uint32_t*)g_Xhi + (size_t)(t - 1) * (Bb * Hh / 2);
                srcL = (const uint32_t*)g_Xlo + (size_t)(t - 1) * (Bb * Hh / 2);
            } else {
                srcH = (const uint32_t*)g_hbh[t & 1];
                srcL = (const uint32_t*)g_hbl[t & 1];
            }
#pragma unroll
            for (int c = 0; c < 16; c++) {
                const float4* ph = (const float4*)(srcH + bst * 256 + (c * 4 + bss) * 4);
                const float4* pl = (const float4*)(srcL + bst * 256 + (c * 4 + bss) * 4);
                uint32_t off = c * 4096 + swoff(bst, bss);
                *(float4*)(smB + off) = __ldcg(ph);
                *(float4*)(smB + 65536 + off) = __ldcg(pl);
            }
        }
        __syncthreads();

        if (t > 0) {
            float acc[2][2][4];
#pragma unroll
            for (int u = 0; u < 2; u++)
#pragma unroll
                for (int nn = 0; nn < 2; nn++)
#pragma unroll
                    for (int i = 0; i < 4; i++) acc[u][nn][i] = 0.0f;
#pragma unroll
            for (int u = 0; u < 2; u++) {
                const int kq = (w >> 2) * 2 + u;
#pragma unroll
                for (int c4 = 0; c4 < 4; c4++) {
                    const int c = kq * 4 + c4;
#pragma unroll
                    for (int ks2 = 0; ks2 < 2; ks2++) {
                        uint32_t ah[4], al[4], bh[4], bl[4];
                        uint32_t ao = c * 1024 + swoff(arow, 2 * ks2 + aseg);
                        ldmx4(ah, sbA + ao);
                        ldmx4(al, sbA + 16384 + ao);
                        uint32_t bo = c * 4096 + swoff(brow, 2 * ks2 + bsegb);
                        ldmx4(bh, sbB + bo);
                        ldmx4(bl, sbB + 65536 + bo);
#pragma unroll
                        for (int nn = 0; nn < 2; nn++) {
                            mma16816(acc[u][nn], ah, bh + 2 * nn);
                            mma16816(acc[u][nn], ah, bl + 2 * nn);
                            mma16816(acc[u][nn], al, bh + 2 * nn);
                        }
                    }
                }
            }
            // store partials: red[kq][r][b]
#pragma unroll
            for (int u = 0; u < 2; u++) {
                const int kq = (w >> 2) * 2 + u;
#pragma unroll
                for (int nn = 0; nn < 2; nn++) {
                    const int bc = ntp * 16 + nn * 8 + 2 * (lane & 3);
                    const int r = lane >> 2;
                    *(float2*)&red[(kq * 16 + r) * 72 + bc] =
                        make_float2(acc[u][nn][0], acc[u][nn][1]);
                    *(float2*)&red[(kq * 16 + r + 8) * 72 + bc] =
                        make_float2(acc[u][nn][2], acc[u][nn][3]);
                }
            }
        }
        __syncthreads();

        // activation: thread (hh, b)
        float gv[4];
#pragma unroll
        for (int q = 0; q < 4; q++) {
            float s = xv[q];
            if (t > 0) {
#pragma unroll
                for (int kq = 0; kq < 4; kq++)
                    s += red[(kq * 16 + q * 4 + hh) * 72 + b];
            }
            gv[q] = s;
        }
        float ig = sigapx(gv[0]), fg = sigapx(gv[1]);
        float gg = tanhapx(gv[2]), og = sigapx(gv[3]);
        c_reg = fg * c_reg + ig * gg;
        float hval = og * tanhapx(c_reg);
        __nv_bfloat16 hb = __float2bfloat16(hval);
        __nv_bfloat16 lb = __float2bfloat16(hval - __bfloat162float(hb));
        if (layer == 0) {
            g_Xhi[(size_t)t * (Bb * Hh) + b * Hh + hi] = hb;
            g_Xlo[(size_t)t * (Bb * Hh) + b * Hh + hi] = lb;
        } else {
            g_hbh[(t + 1) & 1][b * Hh + hi] = hb;
            g_hbl[(t + 1) & 1][b * Hh + hi] = lb;
            __stcg(&g_OUT0[((size_t)t * Hh + hi) * Bb + b], hval);
        }
        if (t == Tt - 1) {
            outHid[(size_t)b * Hh + hi] = hval;
            outCell[(size_t)b * Hh + hi] = c_reg;
        }
        __syncthreads();
        if (tid == 0) redrel(myctr);
    }
}

extern "C" void kernel_launch(void* const* d_in, const int* in_sizes, int n_in,
                              void* d_out, int out_size) {
    const float* x = (const float*)d_in[0];
    const float* Wih0 = (const float*)d_in[1];
    const float* Whh0 = (const float*)d_in[2];
    const float* bih0 = (const float*)d_in[3];
    const float* bhh0 = (const float*)d_in[4];
    const float* Wih1 = (const float*)d_in[5];
    const float* Whh1 = (const float*)d_in[6];
    const float* bih1 = (const float*)d_in[7];
    const float* bhh1 = (const float*)d_in[8];
    float* out = (float*)d_out;

    const int recSmem = 163840 + 4 * 16 * 72 * 4;   // 182272
    cudaFuncSetAttribute(k_rec, cudaFuncAttributeMaxDynamicSharedMemorySize, recSmem);

    dim3 thr32(32, 32);

    // layer 0
    k_splitW<<<(Gg * Ii + 255) / 256, 256>>>(Wih0, Gg * Ii);
    k_splitX0<<<dim3(Tt / 32, Ii / 32, Bb), thr32>>>(x);
    k_mma<<<dim3(Gg / 128, Tt / 2), 256>>>(bih0, bhh0, Ii);
    k_reset<<<2, 256>>>();
    k_rec<<<128, 256, recSmem>>>(Whh0, out, 0);

    // layer 1 (g_Xhi/g_Xlo now hold layer-0 h, written by k_rec)
    k_splitW<<<(Gg * Hh + 255) / 256, 256>>>(Wih1, Gg * Hh);
    k_mma<<<dim3(Gg / 128, Tt / 2), 256>>>(bih1, bhh1, Hh);
    k_reset<<<2, 256>>>();
    k_rec<<<128, 256, recSmem>>>(Whh1, out, 1);

    // final transpose to out[b][t][h]
    k_tro<<<dim3(Hh / 32, Bb / 32, Tt), thr32>>>(out);
}

// round 16
// speedup vs baseline: 1.5027x; 1.0362x over previous
#include <cuda_runtime.h>
#include <cuda_bf16.h>
#include <math.h>
#include <cstdint>

typedef unsigned long long ull;

#define Bb 64
#define Tt 1024
#define Ii 256
#define Hh 512
#define Gg 2048

// ---- scratch (device globals) ----
__device__ float g_XP[(size_t)Tt * Gg * Bb];
__device__ float g_OUT0[(size_t)Tt * Hh * Bb];
__device__ unsigned g_ctr[512];
__device__ __nv_bfloat16 g_Whi[(size_t)Gg * Hh], g_Wlo[(size_t)Gg * Hh];
__device__ __nv_bfloat16 g_Xhi[(size_t)Tt * Bb * Hh], g_Xlo[(size_t)Tt * Bb * Hh];
__device__ __nv_bfloat16 g_hbh[2][Bb * Hh], g_hbl[2][Bb * Hh];

__device__ __forceinline__ float tanhapx(float x) {
    float y; asm("tanh.approx.f32 %0, %1;" : "=f"(y) : "f"(x)); return y;
}
__device__ __forceinline__ float sigapx(float x) { return 0.5f * tanhapx(0.5f * x) + 0.5f; }
__device__ __forceinline__ unsigned ldacq(const unsigned* p) {
    unsigned v; asm volatile("ld.global.acquire.gpu.b32 %0, [%1];" : "=r"(v) : "l"(p)); return v;
}
__device__ __forceinline__ void redrel(unsigned* p) {
    asm volatile("red.release.gpu.global.add.u32 [%0], 1;" :: "l"(p));
}
__device__ __forceinline__ uint32_t s2u(const void* p) {
    uint32_t a;
    asm("{ .reg .u64 t; cvta.to.shared.u64 t, %1; cvt.u32.u64 %0, t; }" : "=r"(a) : "l"(p));
    return a;
}
__device__ __forceinline__ void mma16816(float* d, const uint32_t* a, const uint32_t* b) {
    asm volatile(
        "mma.sync.aligned.m16n8k16.row.col.f32.bf16.bf16.f32 "
        "{%0,%1,%2,%3}, {%4,%5,%6,%7}, {%8,%9}, {%0,%1,%2,%3};"
        : "+f"(d[0]), "+f"(d[1]), "+f"(d[2]), "+f"(d[3])
        : "r"(a[0]), "r"(a[1]), "r"(a[2]), "r"(a[3]), "r"(b[0]), "r"(b[1]));
}
__device__ __forceinline__ void ldmx4(uint32_t* r, uint32_t addr) {
    asm volatile("ldmatrix.sync.aligned.m8n8.x4.shared.b16 {%0,%1,%2,%3}, [%4];"
                 : "=r"(r[0]), "=r"(r[1]), "=r"(r[2]), "=r"(r[3]) : "r"(addr));
}
// row-tile of 64B rows; 16B seg swizzled by row (validated in R12/R14)
__device__ __forceinline__ uint32_t swoff(int r, int s) {
    return (uint32_t)(r * 64 + (((s ^ ((r >> 1) & 3)) & 3) << 4));
}

// ---- split W: fp32 [g][k] -> bf16 hi/lo ----
__global__ void k_splitW(const float* __restrict__ W, int n) {
    int i = blockIdx.x * 256 + threadIdx.x;
    if (i < n) {
        float v = W[i];
        __nv_bfloat16 h = __float2bfloat16(v);
        g_Whi[i] = h;
        g_Wlo[i] = __float2bfloat16(v - __bfloat162float(h));
    }
}

// ---- split+transpose x[b][k][t] -> Xhi/lo[t][b][k] (K=Ii) ----
__global__ void k_splitX0(const float* __restrict__ x) {
    __shared__ float tile[32][33];
    int t0 = blockIdx.x * 32, k0 = blockIdx.y * 32, b = blockIdx.z;
    int tx = threadIdx.x, ty = threadIdx.y;
    tile[ty][tx] = x[((size_t)b * Ii + k0 + ty) * Tt + t0 + tx];
    __syncthreads();
    float v = tile[tx][ty];
    size_t d = ((size_t)(t0 + ty) * Bb + b) * Ii + k0 + tx;
    __nv_bfloat16 h = __float2bfloat16(v);
    g_Xhi[d] = h;
    g_Xlo[d] = __float2bfloat16(v - __bfloat162float(h));
}

// ---- HMMA input GEMM (unchanged from R12/R14) ----
__global__ void __launch_bounds__(256) k_mma(const float* __restrict__ bih,
                                             const float* __restrict__ bhh, int KD) {
    __shared__ uint8_t smb[32768];
    const uint32_t sb = s2u(smb);
    const int tid = threadIdx.x, wid = tid >> 5, lane = tid & 31;
    const int g0 = blockIdx.x * 128, t0 = blockIdx.y * 2;
    const int K2 = KD >> 1;
    const int nc = KD >> 5;

    const uint32_t* Whi = (const uint32_t*)g_Whi;
    const uint32_t* Wlo = (const uint32_t*)g_Wlo;
    const uint32_t* Xhi = (const uint32_t*)g_Xhi;
    const uint32_t* Xlo = (const uint32_t*)g_Xlo;

    float acc[16][4];
#pragma unroll
    for (int q = 0; q < 16; q++)
#pragma unroll
        for (int i = 0; i < 4; i++) acc[q][i] = 0.0f;

    const int arow = wid * 16 + (lane & 15);
    const int aseg = lane >> 4;
    const int bsub = ((lane >> 4) << 3) + (lane & 7);
    const int bseg = (lane >> 3) & 1;

    for (int c = 0; c < nc; c++) {
        __syncthreads();
#pragma unroll
        for (int i = 0; i < 2; i++) {
            int idx = i * 256 + tid, r = idx >> 2, s = idx & 3;
            size_t gw = (size_t)(g0 + r) * K2 + c * 16 + s * 4;
            uint32_t so = swoff(r, s);
            *(float4*)(smb + so) = *(const float4*)(Whi + gw);
            *(float4*)(smb + 8192 + so) = *(const float4*)(Wlo + gw);
        }
#pragma unroll
        for (int i = 0; i < 2; i++) {
            int idx = i * 256 + tid, r = idx >> 2, s = idx & 3;
            int t = t0 + (r >> 6), b = r & 63;
            size_t gw = ((size_t)t * Bb + b) * K2 + c * 16 + s * 4;
            uint32_t so = swoff(r, s);
            *(float4*)(smb + 16384 + so) = *(const float4*)(Xhi + gw);
            *(float4*)(smb + 24576 + so) = *(const float4*)(Xlo + gw);
        }
        __syncthreads();

#pragma unroll
        for (int ks2 = 0; ks2 < 2; ks2++) {
            uint32_t ah[4], al[4];
            {
                uint32_t ao = swoff(arow, 2 * ks2 + aseg);
                ldmx4(ah, sb + ao);
                ldmx4(al, sb + 8192 + ao);
            }
#pragma unroll
            for (int p = 0; p < 8; p++) {
                uint32_t bh[4], bl[4];
                uint32_t bo = swoff(p * 16 + bsub, 2 * ks2 + bseg);
                ldmx4(bh, sb + 16384 + bo);
                ldmx4(bl, sb + 24576 + bo);
                mma16816(acc[2 * p], ah, bh);
                mma16816(acc[2 * p], ah, bl);
                mma16816(acc[2 * p], al, bh);
                mma16816(acc[2 * p + 1], ah, bh + 2);
                mma16816(acc[2 * p + 1], ah, bl + 2);
                mma16816(acc[2 * p + 1], al, bh + 2);
            }
        }
    }

    const int gr = g0 + wid * 16 + (lane >> 2);
    const float bias0 = bih[gr] + bhh[gr];
    const float bias8 = bih[gr + 8] + bhh[gr + 8];
    const int cw = lane & 3;
#pragma unroll
    for (int q = 0; q < 16; q++) {
        const int nb = q * 8;
        const int t = t0 + (nb >> 6);
        const int b0 = (nb & 63) + 2 * cw;
        float* dst = g_XP + ((size_t)t * Gg + gr) * Bb + b0;
        *(float2*)dst = make_float2(acc[q][0] + bias0, acc[q][1] + bias0);
        *(float2*)(dst + (size_t)8 * Bb) = make_float2(acc[q][2] + bias8, acc[q][3] + bias8);
    }
}

// ---- out transpose ----
__global__ void k_tro(float* __restrict__ out) {
    __shared__ float tile[32][33];
    int h0 = blockIdx.x * 32, b0 = blockIdx.y * 32, t = blockIdx.z;
    int tx = threadIdx.x, ty = threadIdx.y;
    tile[ty][tx] = g_OUT0[((size_t)t * Hh + h0 + ty) * Bb + b0 + tx];
    __syncthreads();
    out[((size_t)(b0 + ty) * Tt + t) * Hh + h0 + tx] = tile[tx][ty];
}

// ---- reset counters ----
__global__ void k_reset() {
    int tid = blockIdx.x * blockDim.x + threadIdx.x;
    if (tid < 512) g_ctr[tid] = 0u;
}

// ---- HMMA persistent recurrence: 128 blocks x 512 thr ----
// block j owns h 4j..4j+3 -> 16 gate rows (local r = q*4+hh).
// warp w (16 warps): n-pair ntp=w&3 (16 b), k-quarter kq=w>>2. red over 4 kq.
// sync: 8 spread counters; block j arrives at ctr[(j&7)*64]; tid<8 poll.
__global__ void __launch_bounds__(512, 1) k_rec(const float* __restrict__ Whh,
                                                float* __restrict__ dout, int layer) {
    extern __shared__ uint8_t smx[];
    uint8_t* smA = smx;                  // Ahi 16K | Alo 16K
    uint8_t* smB = smx + 32768;          // Bhi 64K | Blo 64K
    float* red = (float*)(smx + 163840); // [4 kq][16 r][72]
    const uint32_t sbA = s2u(smA), sbB = s2u(smB);
    const int tid = threadIdx.x, w = tid >> 5, lane = tid & 31;
    const int j = blockIdx.x;
    const int hh = (tid >> 6) & 3, b = tid & 63;   // activation role (tid<256)
    const int hi = j * 4 + hh;

    // stage A once: 16 rows x 512 k, bf16 hi/lo, chunked swizzle
    for (int idx = tid; idx < 8192; idx += 512) {
        int r = idx & 15, k = idx >> 4;
        float v = Whh[(size_t)((r >> 2) * Hh + j * 4 + (r & 3)) * Hh + k];
        __nv_bfloat16 hb = __float2bfloat16(v);
        __nv_bfloat16 lb = __float2bfloat16(v - __bfloat162float(hb));
        uint32_t off = (k >> 5) * 1024 + swoff(r, (k >> 3) & 3) + (k & 7) * 2;
        *(__nv_bfloat16*)(smA + off) = hb;
        *(__nv_bfloat16*)(smA + 16384 + off) = lb;
    }
    __syncthreads();

    const int ntp = w & 3, kq = w >> 2;
    const int arow = lane & 15, aseg = lane >> 4;
    const int bsub = ((lane >> 4) << 3) + (lane & 7);
    const int bsegb = (lane >> 3) & 1;
    const int brow = ntp * 16 + bsub;
    // staging role: tid<256 -> hi buffer, tid>=256 -> lo buffer
    const int sh = tid >> 8;                 // 0 = hi, 1 = lo
    const int bst = (tid & 255) >> 2, bss = tid & 3;

    float c_reg = 0.0f;
    float* outHid = dout + (size_t)Bb * Tt * Hh + (size_t)layer * Bb * Hh;
    float* outCell = outHid + 2 * (size_t)Bb * Hh;
    unsigned* myctr = &g_ctr[(j & 7) * 64];

    for (int t = 0; t < Tt; t++) {
        const float* xpt = g_XP + (size_t)t * Gg * Bb;
        float xv[4];
        if (tid < 256) {
#pragma unroll
            for (int q = 0; q < 4; q++)
                xv[q] = __ldcg(&xpt[(size_t)(q * Hh + hi) * Bb + b]);
        }

        if (t > 0) {
            // rendezvous: all 128 blocks published step t-1
            if (tid < 8) {
                const unsigned tgt = 16u * (unsigned)t;
                const unsigned* cp = &g_ctr[tid * 64];
                while (ldacq(cp) < tgt) { }
            }
            __syncthreads();
            // stage B: h[t-1] hi/lo (threads split across the two buffers)
            const uint32_t* src;
            if (layer == 0) {
                src = (const uint32_t*)(sh ? g_Xlo : g_Xhi) + (size_t)(t - 1) * (Bb * Hh / 2);
            } else {
                src = (const uint32_t*)(sh ? g_hbl[t & 1] : g_hbh[t & 1]);
            }
            uint8_t* dstB = smB + sh * 65536;
#pragma unroll
            for (int c = 0; c < 16; c++) {
                const float4* p = (const float4*)(src + bst * 256 + (c * 4 + bss) * 4);
                *(float4*)(dstB + c * 4096 + swoff(bst, bss)) = __ldcg(p);
            }
        }
        __syncthreads();

        if (t > 0) {
            float acc[2][4];
#pragma unroll
            for (int nn = 0; nn < 2; nn++)
#pragma unroll
                for (int i = 0; i < 4; i++) acc[nn][i] = 0.0f;
#pragma unroll
            for (int c4 = 0; c4 < 4; c4++) {
                const int c = kq * 4 + c4;
#pragma unroll
                for (int ks2 = 0; ks2 < 2; ks2++) {
                    uint32_t ah[4], al[4], bh[4], bl[4];
                    uint32_t ao = c * 1024 + swoff(arow, 2 * ks2 + aseg);
                    ldmx4(ah, sbA + ao);
                    ldmx4(al, sbA + 16384 + ao);
                    uint32_t bo = c * 4096 + swoff(brow, 2 * ks2 + bsegb);
                    ldmx4(bh, sbB + bo);
                    ldmx4(bl, sbB + 65536 + bo);
#pragma unroll
                    for (int nn = 0; nn < 2; nn++) {
                        mma16816(acc[nn], ah, bh + 2 * nn);
                        mma16816(acc[nn], ah, bl + 2 * nn);
                        mma16816(acc[nn], al, bh + 2 * nn);
                    }
                }
            }
            // store partials: red[kq][r][b]
#pragma unroll
            for (int nn = 0; nn < 2; nn++) {
                const int bc = ntp * 16 + nn * 8 + 2 * (lane & 3);
                const int r = lane >> 2;
                *(float2*)&red[(kq * 16 + r) * 72 + bc] =
                    make_float2(acc[nn][0], acc[nn][1]);
                *(float2*)&red[(kq * 16 + r + 8) * 72 + bc] =
                    make_float2(acc[nn][2], acc[nn][3]);
            }
        }
        __syncthreads();

        if (tid < 256) {
            // activation: thread (hh, b)
            float gv[4];
#pragma unroll
            for (int q = 0; q < 4; q++) {
                float s = xv[q];
                if (t > 0) {
#pragma unroll
                    for (int k2 = 0; k2 < 4; k2++)
                        s += red[(k2 * 16 + q * 4 + hh) * 72 + b];
                }
                gv[q] = s;
            }
            float ig = sigapx(gv[0]), fg = sigapx(gv[1]);
            float gg = tanhapx(gv[2]), og = sigapx(gv[3]);
            c_reg = fg * c_reg + ig * gg;
            float hval = og * tanhapx(c_reg);
            __nv_bfloat16 hb = __float2bfloat16(hval);
            __nv_bfloat16 lb = __float2bfloat16(hval - __bfloat162float(hb));
            if (layer == 0) {
                g_Xhi[(size_t)t * (Bb * Hh) + b * Hh + hi] = hb;
                g_Xlo[(size_t)t * (Bb * Hh) + b * Hh + hi] = lb;
            } else {
                g_hbh[(t + 1) & 1][b * Hh + hi] = hb;
                g_hbl[(t + 1) & 1][b * Hh + hi] = lb;
                __stcg(&g_OUT0[((size_t)t * Hh + hi) * Bb + b], hval);
            }
            if (t == Tt - 1) {
                outHid[(size_t)b * Hh + hi] = hval;
                outCell[(size_t)b * Hh + hi] = c_reg;
            }
        }
        __syncthreads();
        if (tid == 0) redrel(myctr);
    }
}

extern "C" void kernel_launch(void* const* d_in, const int* in_sizes, int n_in,
                              void* d_out, int out_size) {
    const float* x = (const float*)d_in[0];
    const float* Wih0 = (const float*)d_in[1];
    const float* Whh0 = (const float*)d_in[2];
    const float* bih0 = (const float*)d_in[3];
    const float* bhh0 = (const float*)d_in[4];
    const float* Wih1 = (const float*)d_in[5];
    const float* Whh1 = (const float*)d_in[6];
    const float* bih1 = (const float*)d_in[7];
    const float* bhh1 = (const float*)d_in[8];
    float* out = (float*)d_out;

    const int recSmem = 163840 + 4 * 16 * 72 * 4;   // 182272
    cudaFuncSetAttribute(k_rec, cudaFuncAttributeMaxDynamicSharedMemorySize, recSmem);

    dim3 thr32(32, 32);

    // layer 0
    k_splitW<<<(Gg * Ii + 255) / 256, 256>>>(Wih0, Gg * Ii);
    k_splitX0<<<dim3(Tt / 32, Ii / 32, Bb), thr32>>>(x);
    k_mma<<<dim3(Gg / 128, Tt / 2), 256>>>(bih0, bhh0, Ii);
    k_reset<<<2, 256>>>();
    k_rec<<<128, 512, recSmem>>>(Whh0, out, 0);

    // layer 1 (g_Xhi/g_Xlo now hold layer-0 h, written by k_rec)
    k_splitW<<<(Gg * Hh + 255) / 256, 256>>>(Wih1, Gg * Hh);
    k_mma<<<dim3(Gg / 128, Tt / 2), 256>>>(bih1, bhh1, Hh);
    k_reset<<<2, 256>>>();
    k_rec<<<128, 512, recSmem>>>(Whh1, out, 1);

    // final transpose to out[b][t][h]
    k_tro<<<dim3(Hh / 32, Bb / 32, Tt), thr32>>>(out);
}